// round 15
// baseline (speedup 1.0000x reference)
#include <cuda_runtime.h>
#include <cuda_bf16.h>

// CorrectedHistogramLoss — R15: REDG histogram (R14 fixed).
// R14 bug: reduce_pass summed PACKED u32 words across 1216 groups, so the
// low u16 field overflowed into the high field (64M total counts >> 2^16).
// Fix: extract each u16 field per group word FIRST, accumulate extracted
// values in u32 (max 64M < 2^32).
// Hist: each warp-pair owns a 128-slot u32 global array (two u16 fields,
// scale 2^5, even/odd-pair dual copies); atomicAdd with unused result ->
// RED.E.ADD.32 fire-and-forget (1.29 cyc/lane vs ATOMS 2 cyc/lane).
// reduce_pass also re-zeroes g_part for the next graph replay.
// All-integer accumulation -> bitwise deterministic.

#define NBLK 304      // 2 waves on 152 SMs
#define NTHR 256
#define RBINS 64
#define NGRP (NBLK * 4)          // one group per warp-pair (64 threads)
#define WSCALE 32.0f             // 2^5 per-field fixed point
// Per-group field overflow: <=16 elems/thread/hist * 64 thr * 32 = 32768 < 65536.

__device__ unsigned int g_part[NGRP * 128];   // zero-init; re-zeroed by reduce_pass

__device__ __forceinline__ void acc_one(unsigned int* h, float x) {
    float xc = fminf(fmaxf(x, -1.0f), 1.0f);
    float u  = (xc + 1.0f) * 31.5f;          // (x+1)/LAM, LAM = 2/63
    float fl = floorf(u);
    float w  = u - fl;
    int   f  = (int)fl;
    if (w > 0.0f && f < 63) {                // w==0 contributes nothing (strict ineq.)
        unsigned int wa = __float2uint_rn((1.0f - w) * WSCALE);  // bin f   (low field)
        unsigned int wb = __float2uint_rn(w * WSCALE);           // bin f+1 (high field)
        // slots 0..31: even pair (bins 2k lo | 2k+1 hi); 32..63: odd pair (2k+1 lo | 2k+2 hi)
        int slot = (f & 1) ? (32 + ((f - 1) >> 1)) : (f >> 1);
        atomicAdd(h + slot, wa | (wb << 16));   // result unused -> RED.E.ADD.32
    }
}

__global__ void __launch_bounds__(NTHR)
histo_pass(const float* __restrict__ sim, const float* __restrict__ dis, int n) {
    const int tid = threadIdx.x;
    const int gw  = blockIdx.x * 4 + (tid >> 6);   // warp-pair group id

    unsigned int* h0 = g_part + gw * 128;          // hist_plus slots 0..63
    unsigned int* h1 = h0 + 64;                    // hist_minus slots 64..127

    const int nv = n >> 2;
    const int stride = gridDim.x * blockDim.x;
    const float4* s4 = (const float4*)sim;
    const float4* d4 = (const float4*)dis;

    for (int i = blockIdx.x * blockDim.x + tid; i < nv; i += stride) {
        float4 a = s4[i];
        float4 b = d4[i];
        acc_one(h0, a.x); acc_one(h0, a.y); acc_one(h0, a.z); acc_one(h0, a.w);
        acc_one(h1, b.x); acc_one(h1, b.y); acc_one(h1, b.z); acc_one(h1, b.w);
    }
    if (blockIdx.x == 0 && tid == 0) {      // scalar tail (n not a multiple of 4)
        for (int i = nv << 2; i < n; i++) { acc_one(h0, sim[i]); acc_one(h1, dis[i]); }
    }
}

__global__ void __launch_bounds__(1024)
reduce_pass(float* __restrict__ out, int n) {
    __shared__ unsigned int red[4][256];     // [slice][field*128 + slot]
    __shared__ unsigned int fsum[256];       // [field*128 + slot], fields separated
    __shared__ float sc[2 * RBINS];
    __shared__ float so[2 * RBINS];
    __shared__ float warptot[4];
    __shared__ float acc2[2];

    const int tid   = threadIdx.x;
    const int fs    = tid & 255;             // field*128 + slot
    const int slot  = fs & 127;
    const int field = fs >> 7;               // 0 = low u16, 1 = high u16
    const int j     = tid >> 8;              // 0..3 slices over groups
    const int wp    = tid >> 5;
    const int lane  = tid & 31;

    // extract-then-sum over groups g ≡ j (mod 4); each word is read by two
    // threads (one per field) — L1-broadcast. 304 iterations, 2-way ILP.
    unsigned int s0 = 0u, s1 = 0u;
    for (int g = j; g < NGRP; g += 8) {
        unsigned int w0 = g_part[g * 128 + slot];
        unsigned int w1 = g_part[(g + 4) * 128 + slot];   // NGRP%8==0, always valid
        s0 += field ? (w0 >> 16) : (w0 & 0xffffu);
        s1 += field ? (w1 >> 16) : (w1 & 0xffffu);
    }
    red[j][fs] = s0 + s1;

    // re-zero for next graph replay (each (g,slot) hit once: field 0 threads)
    if (field == 0)
        for (int g = j; g < NGRP; g += 4)
            g_part[g * 128 + slot] = 0u;
    __syncthreads();

    if (tid < 256)
        fsum[tid] = red[0][tid] + red[1][tid] + red[2][tid] + red[3][tid];
    __syncthreads();

    // decode (even-pair + odd-pair copies) -> per-bin value, then scan
    float v = 0.0f, x = 0.0f;
    const float inv = 1.0f / ((float)n * WSCALE);
    if (tid < 2 * RBINS) {
        const int h = tid >> 6;
        const int r = tid & 63;
        // even-pair copy: slot h*64 + r/2, field = r&1
        unsigned int sum = fsum[((r & 1) << 7) + h * 64 + (r >> 1)];
        if (r >= 1 && r <= 62) {
            // odd-pair copy: slot h*64 + 32 + k; r odd -> low field, r even -> high
            int k = (r & 1) ? ((r - 1) >> 1) : ((r >> 1) - 1);
            int f2 = (r & 1) ? 0 : 1;
            sum += fsum[(f2 << 7) + h * 64 + 32 + k];
        }
        v = (float)sum * inv;
        x = v;
        #pragma unroll
        for (int off = 1; off < 32; off <<= 1) {       // warp inclusive scan
            float y = __shfl_up_sync(0xffffffffu, x, off);
            if (lane >= off) x += y;
        }
        if (lane == 31) warptot[wp] = x;
    }
    __syncthreads();
    if (tid < 2 * RBINS) {
        if (wp == 1) x += warptot[0];    // 2nd half of hist_plus segment
        if (wp == 3) x += warptot[2];    // 2nd half of hist_minus segment
        sc[tid] = x;
        so[tid] = v;
    }
    __syncthreads();

    const float q = 0.9f, Pp = 0.1f;
    float term = 0.0f;
    if (tid < RBINS) {
        float hpc = sc[tid];
        float hmc = sc[RBINS + tid];
        float hp  = so[tid];
        float hm  = so[RBINS + tid];
        term = q * q * hpc * hm - q * Pp * hpc * hp - q * Pp * hmc * hm + Pp * Pp * hmc * hp;
    }
    #pragma unroll
    for (int off = 16; off > 0; off >>= 1)
        term += __shfl_down_sync(0xffffffffu, term, off);
    if (tid == 0)  acc2[0] = term;
    if (tid == 32) acc2[1] = term;
    __syncthreads();

    if (tid == 0)
        out[0] = (acc2[0] + acc2[1]) / (1.0f - 4.0f * Pp + 4.0f * Pp * Pp);  // /0.64
}

extern "C" void kernel_launch(void* const* d_in, const int* in_sizes, int n_in,
                              void* d_out, int out_size) {
    const float* sim = (const float*)d_in[0];
    const float* dis = (const float*)d_in[1];   // dissim1; dissim2/margin/anchor_swap unused
    int n = in_sizes[0];
    histo_pass<<<NBLK, NTHR>>>(sim, dis, n);
    reduce_pass<<<1, 1024>>>((float*)d_out, n);
}

// round 16
// speedup vs baseline: 1.8827x; 1.8827x over previous
#include <cuda_runtime.h>
#include <cuda_bf16.h>

// CorrectedHistogramLoss — R16: hybrid ATOMS + FMA-enumeration histogram.
// ATOMS path (warps 0-3): R13-proven per-warp packed u16x2 shared atomics,
// LSU-bound at 2 cyc/element-lane. ENUM path (warps 4-7): each lane evaluates
// its own element against all 64 bins with packed f32x2 math (FMA pipe),
// relu via t+|t| (exact). The two paths run on different pipes concurrently
// over disjoint halves of the data -> ~2x the ATOMS-only rate.
// All cross-thread combining is integer -> bitwise deterministic.

#define NBLK 304
#define NTHR 256
#define RBINS 64
#define ASCALE 32.0f           // ATOMS path per-field fixed point (2^5)
#define ESCALE 64.0f           // ENUM quantization of acc(=2*tri) -> tri units /128
#define STRIDEW (NBLK * 4 * 32)  // 1216 warps per path * 32 lanes

__device__ unsigned int g_partA[NBLK * 128];   // ATOMS partials (unit 1/32)
__device__ unsigned int g_partB[NBLK * 128];   // ENUM partials (unit 1/128)

// ---------- ATOMS path (R13-proven) ----------
__device__ __forceinline__ void acc_one(unsigned int* h, float x) {
    float xc = fminf(fmaxf(x, -1.0f), 1.0f);
    float u  = (xc + 1.0f) * 31.5f;          // (x+1)/LAM, LAM = 2/63
    float fl = floorf(u);
    float w  = u - fl;
    int   f  = (int)fl;
    if (w > 0.0f && f < 63) {                // w==0 contributes nothing (strict ineq.)
        unsigned int wa = __float2uint_rn((1.0f - w) * ASCALE);
        unsigned int wb = __float2uint_rn(w * ASCALE);
        int slot = (f & 1) ? (32 + ((f - 1) >> 1)) : (f >> 1);
        atomicAdd(h + slot, wa | (wb << 16));
    }
}

// ---------- ENUM path ----------
__device__ __forceinline__ unsigned long long pack2(float lo, float hi) {
    unsigned long long r;
    asm("mov.b64 %0, {%1, %2};" : "=l"(r) : "f"(lo), "f"(hi));
    return r;
}

// one phase: enumerate one input array over [start,end) vec4 range,
// fold results into smem outAcc[0..63] (bin-indexed) via uniform-addr atomics.
__device__ __forceinline__ void enum_phase(const float4* __restrict__ src,
                                           int start, int end, int we,
                                           unsigned int* outAcc) {
    const unsigned long long SIGN2 = 0x8000000080000000ULL;
    const unsigned long long ABS2  = 0x7FFFFFFF7FFFFFFFULL;
    const unsigned long long ONE2  = pack2(1.0f, 1.0f);
    const int lane = threadIdx.x & 31;

    unsigned long long acc[32];
    #pragma unroll
    for (int j = 0; j < 32; j++) acc[j] = 0ULL;   // 0ULL == packed (0.f,0.f)

    int iters = (end - start + STRIDEW - 1) / STRIDEW;
    int i = start + we * 32 + lane;
    for (int k = 0; k < iters; k++, i += STRIDEW) {
        float u0, u1, u2, u3;
        if (i < end) {
            float4 x = src[i];
            u0 = fminf(fmaxf(fmaf(x.x, 31.5f, 31.5f), 0.0f), 63.0f);
            u1 = fminf(fmaxf(fmaf(x.y, 31.5f, 31.5f), 0.0f), 63.0f);
            u2 = fminf(fmaxf(fmaf(x.z, 31.5f, 31.5f), 0.0f), 63.0f);
            u3 = fminf(fmaxf(fmaf(x.w, 31.5f, 31.5f), 0.0f), 63.0f);
        } else {
            u0 = u1 = u2 = u3 = -1.0e6f;   // contributes 0 to every bin
        }
        unsigned long long up0 = pack2(u0, u0), up1 = pack2(u1, u1);
        unsigned long long up2 = pack2(u2, u2), up3 = pack2(u3, u3);

        #pragma unroll
        for (int j = 0; j < 32; j++) {
            // bin pair (2j, 2j+1), pre-negated
            const unsigned long long c2 = pack2(-(float)(2 * j), -(float)(2 * j + 1));
            #define EVAL(UP)  do {                                                   \
                unsigned long long d2, nd, t2, at, s2;                               \
                asm("add.rn.f32x2 %0, %1, %2;" : "=l"(d2) : "l"(UP), "l"(c2));       \
                asm("or.b64 %0, %1, %2;"       : "=l"(nd) : "l"(d2), "l"(SIGN2));    \
                asm("add.rn.f32x2 %0, %1, %2;" : "=l"(t2) : "l"(ONE2), "l"(nd));     \
                asm("and.b64 %0, %1, %2;"      : "=l"(at) : "l"(t2), "l"(ABS2));     \
                asm("add.rn.f32x2 %0, %1, %2;" : "=l"(s2) : "l"(t2), "l"(at));       \
                asm("add.rn.f32x2 %0, %0, %1;" : "+l"(acc[j]) : "l"(s2));            \
            } while (0)
            EVAL(up0); EVAL(up1); EVAL(up2); EVAL(up3);
            #undef EVAL
        }
    }

    // fold: quantize each packed acc (holds 2*tri sums for bins 2j, 2j+1),
    // uniform-address smem atomics -> ptxas REDUX-aggregates per warp.
    #pragma unroll
    for (int j = 0; j < 32; j++) {
        float lo, hi;
        asm("mov.b64 {%0, %1}, %2;" : "=f"(lo), "=f"(hi) : "l"(acc[j]));
        atomicAdd(&outAcc[2 * j],     __float2uint_rn(lo * ESCALE));
        atomicAdd(&outAcc[2 * j + 1], __float2uint_rn(hi * ESCALE));
    }
}

__global__ void __launch_bounds__(NTHR, 2)
histo_pass(const float* __restrict__ sim, const float* __restrict__ dis, int n) {
    __shared__ unsigned int sh[4 * 128];      // ATOMS per-warp hists
    __shared__ unsigned int enumAcc[128];     // ENUM bin-indexed block totals

    const int tid  = threadIdx.x;
    const int wid  = tid >> 5;
    const int lane = tid & 31;

    for (int i = tid; i < 512; i += NTHR) sh[i] = 0u;
    if (tid < 128) enumAcc[tid] = 0u;
    __syncthreads();

    const int nv  = n >> 2;
    const int nvA = nv >> 1;                  // 50/50 split (rates are equal)
    const float4* s4 = (const float4*)sim;
    const float4* d4 = (const float4*)dis;

    if (wid < 4) {
        // ---- ATOMS path over [0, nvA) ----
        unsigned int* h0 = sh + wid * 128;
        unsigned int* h1 = h0 + 64;
        const int wa = blockIdx.x * 4 + wid;
        for (int i = wa * 32 + lane; i < nvA; i += STRIDEW) {
            float4 a = s4[i];
            float4 b = d4[i];
            acc_one(h0, a.x); acc_one(h0, a.y); acc_one(h0, a.z); acc_one(h0, a.w);
            acc_one(h1, b.x); acc_one(h1, b.y); acc_one(h1, b.z); acc_one(h1, b.w);
        }
        if (blockIdx.x == 0 && tid == 0) {    // scalar tail (n % 4)
            for (int i = nv << 2; i < n; i++) { acc_one(h0, sim[i]); acc_one(h1, dis[i]); }
        }
    } else {
        // ---- ENUM path over [nvA, nv) ----
        const int we = blockIdx.x * 4 + (wid - 4);
        enum_phase(s4, nvA, nv, we, enumAcc);        // hist_plus  -> bins 0..63
        enum_phase(d4, nvA, nv, we, enumAcc + 64);   // hist_minus -> bins 64..127
    }
    __syncthreads();

    if (tid < 128) {
        // decode ATOMS slots (4 warp copies) -> bin-indexed partial
        const int h = tid >> 6;
        const int r = tid & 63;
        unsigned int sum = 0u;
        #pragma unroll
        for (int w = 0; w < 4; w++) {
            const unsigned int* hw = sh + w * 128 + h * 64;
            unsigned int e = hw[r >> 1];
            sum += (r & 1) ? (e >> 16) : (e & 0xffffu);
            if (r >= 1 && r <= 62) {
                int k = (r & 1) ? ((r - 1) >> 1) : ((r >> 1) - 1);
                unsigned int o = hw[32 + k];
                sum += (r & 1) ? (o & 0xffffu) : (o >> 16);
            }
        }
        g_partA[blockIdx.x * 128 + tid] = sum;
        g_partB[blockIdx.x * 128 + tid] = enumAcc[tid];
    }
}

__global__ void __launch_bounds__(1024)
reduce_pass(float* __restrict__ out, int n) {
    __shared__ unsigned int red[8 * 128];
    __shared__ float sc[2 * RBINS];
    __shared__ float so[2 * RBINS];
    __shared__ float warptot[4];
    __shared__ float acc2[2];

    const int tid  = threadIdx.x;
    const int bin  = tid & 127;
    const int j    = tid >> 7;
    const int wp   = tid >> 5;
    const int lane = tid & 31;

    unsigned int a0 = 0u, a1 = 0u, b0 = 0u, b1 = 0u;
    for (int b = j; b < NBLK; b += 16) {
        a0 += g_partA[b * 128 + bin];
        b0 += g_partB[b * 128 + bin];
        if (b + 8 < NBLK) {
            a1 += g_partA[(b + 8) * 128 + bin];
            b1 += g_partB[(b + 8) * 128 + bin];
        }
    }
    // common unit 1/128: A entries are 1/32 -> x4
    red[j * 128 + bin] = (a0 + a1) * 4u + (b0 + b1);
    __syncthreads();

    float v = 0.0f, x = 0.0f;
    const float inv = 1.0f / ((float)n * 128.0f);
    if (tid < 2 * RBINS) {
        unsigned int t = 0u;
        #pragma unroll
        for (int k = 0; k < 8; k++) t += red[k * 128 + tid];
        v = (float)t * inv;
        x = v;
        #pragma unroll
        for (int off = 1; off < 32; off <<= 1) {       // warp inclusive scan
            float y = __shfl_up_sync(0xffffffffu, x, off);
            if (lane >= off) x += y;
        }
        if (lane == 31) warptot[wp] = x;
    }
    __syncthreads();
    if (tid < 2 * RBINS) {
        if (wp == 1) x += warptot[0];    // 2nd half of hist_plus segment
        if (wp == 3) x += warptot[2];    // 2nd half of hist_minus segment
        sc[tid] = x;
        so[tid] = v;
    }
    __syncthreads();

    const float q = 0.9f, Pp = 0.1f;
    float term = 0.0f;
    if (tid < RBINS) {
        float hpc = sc[tid];
        float hmc = sc[RBINS + tid];
        float hp  = so[tid];
        float hm  = so[RBINS + tid];
        term = q * q * hpc * hm - q * Pp * hpc * hp - q * Pp * hmc * hm + Pp * Pp * hmc * hp;
    }
    #pragma unroll
    for (int off = 16; off > 0; off >>= 1)
        term += __shfl_down_sync(0xffffffffu, term, off);
    if (tid == 0)  acc2[0] = term;
    if (tid == 32) acc2[1] = term;
    __syncthreads();

    if (tid == 0)
        out[0] = (acc2[0] + acc2[1]) / (1.0f - 4.0f * Pp + 4.0f * Pp * Pp);  // /0.64
}

extern "C" void kernel_launch(void* const* d_in, const int* in_sizes, int n_in,
                              void* d_out, int out_size) {
    const float* sim = (const float*)d_in[0];
    const float* dis = (const float*)d_in[1];   // dissim1; dissim2/margin/anchor_swap unused
    int n = in_sizes[0];
    histo_pass<<<NBLK, NTHR>>>(sim, dis, n);
    reduce_pass<<<1, 1024>>>((float*)d_out, n);
}